// round 1
// baseline (speedup 1.0000x reference)
#include <cuda_runtime.h>

#define NH 128
#define NI 64
#define NO 10
#define NB 128

// Persistent per-batch-chain RNN scan.
// grid = 128 CTAs (one batch row each), block = 128 threads (thread j owns
// hidden output column j). Whh/Wxh columns live in registers; h and x live in
// shared with double buffering; one barrier per timestep.
__global__ void __launch_bounds__(NH, 1) rnn_scan_kernel(
    const float* __restrict__ x,    // [S, B, NI]
    const float* __restrict__ Wxh,  // [NI, NH]
    const float* __restrict__ Whh,  // [NH, NH]
    const float* __restrict__ Why,  // [NH, NO]
    const float* __restrict__ bh,   // [NH]
    const float* __restrict__ by,   // [NO]
    float* __restrict__ out,        // logits [B,NO] then h [S,B,NH]
    int seq)
{
    const int b = blockIdx.x;
    const int j = threadIdx.x;

    // ---- load this thread's weight columns into registers ----
    float whh[NH];
#pragma unroll
    for (int k = 0; k < NH; k++) whh[k] = Whh[k * NH + j];
    float wxh[NI];
#pragma unroll
    for (int i = 0; i < NI; i++) wxh[i] = Wxh[i * NH + j];
    const float bias = bh[j];

    __shared__ __align__(16) float hsh[2][NH];
    __shared__ __align__(16) float xsh[2][NI];

    hsh[0][j] = 0.0f;

    const float* xbase = x + (long long)b * NI;  // + t * NB * NI per step

    // preload x(0) into xsh[0]
    if (j < NI / 4) {
        reinterpret_cast<float4*>(xsh[0])[j] =
            reinterpret_cast<const float4*>(xbase)[j];
    }
    __syncthreads();

    // pipeline register holds x(t+1); STS'd at top of step t, LDG refills x(t+2)
    float4 xr = make_float4(0.f, 0.f, 0.f, 0.f);
    if (j < NI / 4 && seq > 1) {
        xr = reinterpret_cast<const float4*>(xbase + (long long)NB * NI)[j];
    }

    float* h_out = out + NB * NO;  // h region after logits
    int hb = 0;

    for (int t = 0; t < seq; t++) {
        // ---- x prefetch pipeline (threads 0..15 only) ----
        if (j < NI / 4) {
            reinterpret_cast<float4*>(xsh[(t + 1) & 1])[j] = xr;  // x(t+1)
            if (t + 2 < seq) {
                xr = reinterpret_cast<const float4*>(
                         xbase + (long long)(t + 2) * NB * NI)[j];
            }
        }

        // ---- 192-term dot product: h_prev @ Whh[:,j] + x_t @ Wxh[:,j] ----
        float a0 = bias, a1 = 0.f, a2 = 0.f, a3 = 0.f;
        const float4* h4 = reinterpret_cast<const float4*>(hsh[hb]);
#pragma unroll
        for (int k = 0; k < NH / 4; k++) {
            float4 hv = h4[k];  // broadcast LDS.128
            a0 = fmaf(hv.x, whh[4 * k + 0], a0);
            a1 = fmaf(hv.y, whh[4 * k + 1], a1);
            a2 = fmaf(hv.z, whh[4 * k + 2], a2);
            a3 = fmaf(hv.w, whh[4 * k + 3], a3);
        }
        const float4* x4 = reinterpret_cast<const float4*>(xsh[t & 1]);
#pragma unroll
        for (int i = 0; i < NI / 4; i++) {
            float4 xv = x4[i];  // broadcast LDS.128
            a0 = fmaf(xv.x, wxh[4 * i + 0], a0);
            a1 = fmaf(xv.y, wxh[4 * i + 1], a1);
            a2 = fmaf(xv.z, wxh[4 * i + 2], a2);
            a3 = fmaf(xv.w, wxh[4 * i + 3], a3);
        }
        float v = (a0 + a1) + (a2 + a3);

        // ---- tanh via exp2 (branch-free, ~1e-7 rel err; approx-tanh's 1e-3
        // absolute error would random-walk past tolerance over 2048 steps) ----
        float a = fabsf(v);
        float e = __expf(-2.0f * a);          // MUFU.EX2 path
        float r = (1.0f - e) / (1.0f + e);    // MUFU.RCP path
        float h = copysignf(r, v);

        h_out[((long long)t * NB + b) * NH + j] = h;  // coalesced 512B store
        hsh[hb ^ 1][j] = h;
        __syncthreads();
        hb ^= 1;
    }

    // ---- logits = h_last @ Why + by (tiny tail) ----
    if (j < NO) {
        float acc = by[j];
#pragma unroll 8
        for (int k = 0; k < NH; k++)
            acc = fmaf(hsh[hb][k], Why[k * NO + j], acc);
        out[b * NO + j] = acc;
    }
}

extern "C" void kernel_launch(void* const* d_in, const int* in_sizes, int n_in,
                              void* d_out, int out_size) {
    const float* x   = (const float*)d_in[0];
    const float* Wxh = (const float*)d_in[1];
    const float* Whh = (const float*)d_in[2];
    const float* Why = (const float*)d_in[3];
    const float* bh  = (const float*)d_in[4];
    const float* by  = (const float*)d_in[5];
    float* out = (float*)d_out;

    int seq = in_sizes[0] / (NB * NI);  // 2048

    rnn_scan_kernel<<<NB, NH>>>(x, Wxh, Whh, Why, bh, by, out, seq);
}